// round 16
// baseline (speedup 1.0000x reference)
#include <cuda_runtime.h>
#include <math_constants.h>

// FINAL — champion (8 clean runs: kernel 51.9-55.4us, mode ~52.2us, best
// bench 61.9us; DRAM 83-85%, 6.33-6.74 TB/s = 97-98% of the B300 LTS fabric
// ceiling of ~6300 B/cyc). Converged: the identical binary's resampled
// distribution is stationary and all structural variants sit within it.
//
// Output = one-hot(argmax over F of logits+gumbel); forward-exact vs reference:
//   * straight-through mask (y_hard - sg(y_soft) + y_soft) is numerically
//     exact 0 off-argmax and ~1 (within 2^-24) at the argmax;
//   * softmax is monotone, so argmax(softmax((l+g)/tau)) = argmax(l+g);
//   * the top-K-smallest-then-zero step only selects entries that are already
//     exactly 0 (K=104857 << 1046528 zeros per batch) -> no-op.
//
// Traffic floor: 256 MiB read + 128 MiB write = 384 MiB. One warp per row,
// 8 LDG.128 per warp, butterfly argmax, STG.128 one-hot.
// Exhausted levers (R2-R15): persistent grid, forced occupancy, source-level
// MLP batching, 2-row software pipeline, ldcs/stcs hints — all within +-2%.
// TMA / 2-pass splits / instruction micro-opts ruled out analytically
// (shared path-independent LTS cap; issue=20% hides ALU work entirely).

static constexpr int Bc = 32;
static constexpr int Sc = 2048;
static constexpr int Fc = 512;
static constexpr int ROWS = Bc * Sc;          // 65536 rows
static constexpr int F4  = Fc / 4;            // 128 float4 per row

__global__ __launch_bounds__(256)
void onehot_argmax_kernel(const float4* __restrict__ logits,
                          const float4* __restrict__ gumbel,
                          float4* __restrict__ out) {
    const int warp = (blockIdx.x * blockDim.x + threadIdx.x) >> 5;
    const int lane = threadIdx.x & 31;
    if (warp >= ROWS) return;

    const size_t base = (size_t)warp * F4;

    float best = -CUDART_INF_F;
    int   bidx = 0;

    // Each lane handles 4 float4s: positions c*32 + lane (c = 0..3).
    // Indices strictly increase within a lane, so strict ">" gives the
    // first-index tie-break per lane; cross-lane tie-break in the butterfly.
    #pragma unroll
    for (int c = 0; c < 4; c++) {
        const int p = c * 32 + lane;
        const float4 a = logits[base + p];
        const float4 g = gumbel[base + p];
        const float s0 = a.x + g.x;
        const float s1 = a.y + g.y;
        const float s2 = a.z + g.z;
        const float s3 = a.w + g.w;
        const int e = p * 4;
        if (s0 > best) { best = s0; bidx = e;     }
        if (s1 > best) { best = s1; bidx = e + 1; }
        if (s2 > best) { best = s2; bidx = e + 2; }
        if (s3 > best) { best = s3; bidx = e + 3; }
    }

    // Butterfly reduction: max by value, lowest index on ties (== jnp.argmax).
    // Lexicographic max is associative+commutative, so every lane converges to
    // the row argmax — no broadcast needed before the store phase.
    #pragma unroll
    for (int off = 16; off; off >>= 1) {
        const float ov = __shfl_xor_sync(0xffffffffu, best, off);
        const int   oi = __shfl_xor_sync(0xffffffffu, bidx, off);
        if (ov > best || (ov == best && oi < bidx)) { best = ov; bidx = oi; }
    }

    // Compose + write the one-hot row (each lane owns its float4s; no RMW).
    #pragma unroll
    for (int c = 0; c < 4; c++) {
        const int p = c * 32 + lane;
        const int e = p * 4;
        float4 o;
        o.x = (e     == bidx) ? 1.0f : 0.0f;
        o.y = (e + 1 == bidx) ? 1.0f : 0.0f;
        o.z = (e + 2 == bidx) ? 1.0f : 0.0f;
        o.w = (e + 3 == bidx) ? 1.0f : 0.0f;
        out[base + p] = o;
    }
}

extern "C" void kernel_launch(void* const* d_in, const int* in_sizes, int n_in,
                              void* d_out, int out_size) {
    const float4* logits = (const float4*)d_in[0];
    const float4* gumbel = (const float4*)d_in[1];
    float4* out = (float4*)d_out;

    const int threads = 256;
    const int warps_per_block = threads / 32;
    const int blocks = (ROWS + warps_per_block - 1) / warps_per_block;  // 8192
    onehot_argmax_kernel<<<blocks, threads>>>(logits, gumbel, out);
}